// round 12
// baseline (speedup 1.0000x reference)
#include <cuda_runtime.h>

#define NB 256

// ---------------- scratch (static device globals; no allocation) ----------------
__device__ float g_T0[512 * 512];
__device__ float g_T1[512 * 512];
__device__ float g_Apow[10 * 512 * 512];
__device__ float g_Bcat[4 * 512 * 256];
__device__ float g_Q[512];
__device__ float g_S[17 * 24 * 256];
__device__ float g_wv[306 * 256];
__device__ float g_pS[8 * 512 * 512];
__device__ float g_pC[8 * 512 * 512];
__device__ float g_pD[8 * 512 * 256];

// ---------------- software grid barrier (per-stage slot, replay-safe) ------------
__device__ unsigned g_cnt[48];
__device__ volatile unsigned g_flag[48];

__device__ __forceinline__ void gbar(int s)
{
    __threadfence();
    __syncthreads();
    if (threadIdx.x == 0) {
        unsigned old = g_flag[s];
        unsigned v = atomicAdd(&g_cnt[s], 1u);
        if (v == NB - 1u) {
            g_cnt[s] = 0;
            __threadfence();
            g_flag[s] = old + 1u;
        } else {
            while (g_flag[s] == old) __nanosleep(64);
        }
    }
    __syncthreads();
    __threadfence();
}

// ================= GEMM tile routine (128x64, 8x4 micro, double-buffered) ========
struct GemmDesc {
    const float* A; long long Ars; int Amode;   // 0: A[m*Ars+k]; 1: cat4 [(k>>8)*131072 + m*256 + (k&255)]
    const float* B; long long Bks; long long Bjs;
    int Bmode;                                  // 0: B[k+n*Bjs]; 1: B[k*Bks+n]; 2: Ucat(u_history)
    float* C; long long Cis; long long Cjs;
    float* part; long long slab;
    int M, N, K, gx, gy, gz;
};

#define AS(buf,kk,i) As[(((buf)*16 + (kk)) * 132) + (i)]
#define BS(buf,kk,i) Bs[(((buf)*16 + (kk)) * 72)  + (i)]

__device__ void gemm_block(const GemmDesc& d, int r, float* As, float* Bs)
{
    __syncthreads();   // protect smem reuse across consecutive calls

    const int tid = threadIdx.x;
    const int bx = r % d.gx;
    const int by = (r / d.gx) % d.gy;
    const int z  = r / (d.gx * d.gy);
    const int bm = by * 128;
    const int bn = bx * 64;
    const int Kc = d.K / d.gz;
    const int kbeg = z * Kc;
    const int nt = Kc >> 4;

    const int arow = tid >> 1;
    const int akq  = (tid & 1) * 8;
    const int btn  = tid >> 2;
    const int btk  = (tid & 3) * 4;
    const int bkk  = tid >> 4;
    const int bn4  = (tid & 15) * 4;
    const int ty = tid >> 4, tx = tid & 15;

    float4 ax, ay, bv;

    auto loadA8 = [&](int kt) {
        int k = kbeg + kt + akq;
        const float* p = (d.Amode == 0)
            ? d.A + (long long)(bm + arow) * d.Ars + k
            : d.A + (long long)(k >> 8) * 131072 + (long long)(bm + arow) * 256 + (k & 255);
        ax = *(const float4*)p;
        ay = *(const float4*)(p + 4);
    };
    auto loadB4 = [&](int kt) {
        if (d.Bmode == 1) {
            bv = *(const float4*)(d.B + (long long)(kbeg + kt + bkk) * d.Bks + bn + bn4);
        } else if (d.Bmode == 0) {
            int n = bn + btn;
            bv = (n < d.N) ? *(const float4*)(d.B + (long long)(kbeg + kt + btk)
                                                + (long long)n * d.Bjs)
                           : make_float4(0.f, 0.f, 0.f, 0.f);
        } else {
            int n = bn + btn;
            int k = kbeg + kt + btk;
            if (n < d.N) {
                int tu = 2047 - 4 * n - (k >> 8);
                bv = *(const float4*)(d.B + (long long)tu * 256 + (k & 255));
            } else bv = make_float4(0.f, 0.f, 0.f, 0.f);
        }
    };
    auto stAB = [&](int buf) {
        float av[8] = {ax.x, ax.y, ax.z, ax.w, ay.x, ay.y, ay.z, ay.w};
        #pragma unroll
        for (int j = 0; j < 8; j++) AS(buf, akq + j, arow) = av[j];
        if (d.Bmode == 1) {
            *(float4*)&BS(buf, bkk, bn4) = bv;
        } else {
            float vv[4] = {bv.x, bv.y, bv.z, bv.w};
            #pragma unroll
            for (int j = 0; j < 4; j++) BS(buf, btk + j, btn) = vv[j];
        }
    };

    loadA8(0); loadB4(0);
    stAB(0);
    __syncthreads();

    float acc[8][4] = {};

    for (int t = 0; t < nt; t++) {
        int cur = t & 1;
        if (t + 1 < nt) { loadA8((t + 1) * 16); loadB4((t + 1) * 16); }
        #pragma unroll
        for (int kk = 0; kk < 16; kk++) {
            float4 a4 = *(const float4*)&AS(cur, kk, ty * 8);
            float4 a5 = *(const float4*)&AS(cur, kk, ty * 8 + 4);
            float4 b4 = *(const float4*)&BS(cur, kk, tx * 4);
            float av[8] = {a4.x, a4.y, a4.z, a4.w, a5.x, a5.y, a5.z, a5.w};
            float bw[4] = {b4.x, b4.y, b4.z, b4.w};
            #pragma unroll
            for (int i = 0; i < 8; i++)
                #pragma unroll
                for (int j = 0; j < 4; j++)
                    acc[i][j] = fmaf(av[i], bw[j], acc[i][j]);
        }
        if (t + 1 < nt) {
            __syncthreads();
            stAB(cur ^ 1);
            __syncthreads();
        }
    }

    float* outp = d.part ? d.part + (long long)z * d.slab : d.C;
    if (d.Cjs == 1) {
        int gn = bn + tx * 4;
        if (gn < d.N) {
            #pragma unroll
            for (int i = 0; i < 8; i++) {
                int gm = bm + ty * 8 + i;
                *(float4*)(outp + (long long)gm * d.Cis + gn) =
                    make_float4(acc[i][0], acc[i][1], acc[i][2], acc[i][3]);
            }
        }
    } else {
        #pragma unroll
        for (int j = 0; j < 4; j++) {
            int gn = bn + tx * 4 + j;
            if (gn < d.N) {
                long long base = (long long)(bm + ty * 8) + (long long)gn * d.Cjs;
                *(float4*)(outp + base)     = make_float4(acc[0][j], acc[1][j], acc[2][j], acc[3][j]);
                *(float4*)(outp + base + 4) = make_float4(acc[4][j], acc[5][j], acc[6][j], acc[7][j]);
            }
        }
    }
}

// ---------------- reduce (grid-strided, MLP-8 fast path) -------------------------
struct RedDesc {
    float* dst; const float* part;
    int len; int nz; long long slab;
    const float* Add; long long Adjs; int colMajor;
};

__device__ void red_range(const RedDesc& r, float* qdst)
{
    int n4 = r.len >> 2;
    for (int g = blockIdx.x * 256 + threadIdx.x; g < n4; g += NB * 256) {
        int i = g * 4;
        float4 acc;
        if (r.nz == 8) {
            float4 v[8];
            #pragma unroll
            for (int zz = 0; zz < 8; zz++)
                v[zz] = *(const float4*)(r.part + (long long)zz * r.slab + i);
            acc = v[0];
            #pragma unroll
            for (int zz = 1; zz < 8; zz++) {
                acc.x += v[zz].x; acc.y += v[zz].y; acc.z += v[zz].z; acc.w += v[zz].w;
            }
        } else {
            acc = *(const float4*)(r.part + i);
            for (int zz = 1; zz < r.nz; zz++) {
                float4 v = *(const float4*)(r.part + (long long)zz * r.slab + i);
                acc.x += v.x; acc.y += v.y; acc.z += v.z; acc.w += v.w;
            }
        }
        if (r.Add && r.colMajor) {
            int gm = i & 511, gn = i >> 9;
            const float* ap = r.Add + gm + (long long)gn * r.Adjs;
            acc.x += ap[0]; acc.y += ap[1]; acc.z += ap[2]; acc.w += ap[3];
        }
        *(float4*)(r.dst + i) = acc;
        if (qdst && i < 512) *(float4*)(qdst + i) = acc;
    }
}

// ---------------- small task bodies ----------------------------------------------
__device__ void s_task(int t, const float* __restrict__ phi, const float* __restrict__ ynh,
                       float* __restrict__ S)
{
    int l = t / 24, j = t % 24, p = threadIdx.x;
    float acc = 0.f;
    #pragma unroll
    for (int k = 0; k < 25; k++)
        acc += phi[k * 17 + l] * ynh[(2047 - (2 + j + k)) * 256 + p];
    S[t * 256 + p] = acc;
}

__device__ void wv_task(int b, const float* __restrict__ ynh, const float* __restrict__ S,
                        const float* __restrict__ phi, const float* __restrict__ phit,
                        const float* __restrict__ sig, const float* __restrict__ lam,
                        float* __restrict__ wv)
{
    int p = threadIdx.x;
    float v;
    if (b == 0) {
        v = ynh[2047 * 256 + p];
    } else if (b < 17) {
        int i = b - 1;
        float lam4 = sqrtf(sqrtf(lam[i]));
        float acc = 0.f;
        #pragma unroll
        for (int j = 0; j < 24; j++)
            acc += phit[j * 16 + i] * ynh[(2047 - 1 - j) * 256 + p];
        v = lam4 * acc;
    } else {
        int bb = b - 17, ip = bb / 17, l = bb % 17;
        float s4 = sqrtf(sqrtf(sig[l]));
        if (ip == 0) {
            float acc = 0.f;
            #pragma unroll
            for (int k = 0; k < 25; k++)
                acc += phi[k * 17 + l] * ynh[(2047 - k) * 256 + p];
            v = s4 * acc;
        } else {
            int i = ip - 1;
            float lam4 = sqrtf(sqrtf(lam[i]));
            float acc = 0.f;
            #pragma unroll
            for (int j = 0; j < 24; j++)
                acc += phit[j * 16 + i] * S[(l * 24 + j) * 256 + p];
            v = lam4 * s4 * acc;
        }
    }
    wv[b * 256 + p] = v;
}

__device__ void ut_task(int n, const float* __restrict__ Mm, const float* __restrict__ Mbar,
                        const float* __restrict__ wv, float* __restrict__ out, float* sd)
{
    __syncthreads();
    int p = threadIdx.x;
    float acc = 0.f;
    #pragma unroll 4
    for (int b = 0; b < 17; b++)
        acc += Mbar[((long long)b * 256 + n) * 256 + p] * wv[b * 256 + p];
    #pragma unroll 4
    for (int bb = 0; bb < 289; bb++)
        acc += Mm[((long long)bb * 256 + n) * 256 + p] * wv[(17 + bb) * 256 + p];
    sd[p] = acc;
    __syncthreads();
    for (int st = 128; st > 0; st >>= 1) {
        if (p < st) sd[p] += sd[p + st];
        __syncthreads();
    }
    if (p == 0) out[512 + n] = sd[0];
    __syncthreads();
}

__device__ void tail_task(int row, const float* __restrict__ Cm, const float* __restrict__ ylast,
                          const float* __restrict__ s, const float* __restrict__ q,
                          float* __restrict__ out, float* sd)
{
    __syncthreads();
    int p = row & 255;
    bool isPred = row >= 256;
    const float* cr = Cm + p * 512;
    float acc = 0.f;
    for (int d = threadIdx.x; d < 512; d += 256) {
        float x = isPred ? (q[d] - s[d]) : (-s[d]);
        acc += cr[d] * x;
    }
    sd[threadIdx.x] = acc;
    __syncthreads();
    for (int st = 128; st > 0; st >>= 1) {
        if (threadIdx.x < st) sd[threadIdx.x] += sd[threadIdx.x + st];
        __syncthreads();
    }
    if (threadIdx.x == 0) out[row] = ylast[p] + sd[0];
    __syncthreads();
}

// ================= the persistent kernel =========================================
struct Params {
    const float *A, *Bm, *Cm, *Mm, *Mbar, *sig, *phi, *lam, *phit, *yh, *uh, *ynh;
    float *out;
    float *T0, *T1, *Ap, *Bc, *Qb, *S, *wv, *pS, *pC, *pD;
};

__global__ __launch_bounds__(256, 2) void persist_kernel(Params P)
{
    __shared__ float As[2 * 16 * 132];
    __shared__ float Bs[2 * 16 * 72];

    const long long SQ = 512 * 512;
    const long long HB = 512 * 256;
    int bar = 0;

    GemmDesc gd = {}; gd.gx = gd.gy = gd.gz = 1;
    RedDesc  rd = {};

    auto sqDesc = [&](int k) {
        GemmDesc d = gd;
        const float* src = (k == 0) ? P.A : P.Ap + (long long)(k - 1) * SQ;
        d.A = src; d.Ars = 512; d.Amode = 0;
        d.B = src; d.Bks = 512; d.Bmode = 1;
        d.C = P.Ap + (long long)k * SQ; d.Cis = 512; d.Cjs = 1;
        d.part = P.pS; d.slab = SQ;
        d.M = 512; d.N = 512; d.K = 512; d.gx = 8; d.gy = 4; d.gz = 8;
        return d;
    };
    auto sqRed = [&](int k) {
        RedDesc r = rd;
        r.dst = P.Ap + (long long)k * SQ; r.part = P.pS;
        r.len = (int)SQ; r.nz = 8; r.slab = SQ;
        return r;
    };

    // ---- St0: S tasks + copy B into Bcat slot 0 ----
    for (int t = blockIdx.x; t < 408; t += NB) s_task(t, P.phi, P.ynh, P.S);
    for (int g = blockIdx.x * 256 + threadIdx.x; g < (int)(HB >> 2); g += NB * 256)
        *(float4*)(P.Bc + g * 4) = *(const float4*)(P.Bm + g * 4);
    gbar(bar++);

    // ---- St1: wv ----
    for (int t = blockIdx.x; t < 306; t += NB)
        wv_task(t, P.ynh, P.S, P.phi, P.phit, P.sig, P.lam, P.wv);
    gbar(bar++);

    // ---- St2: ut(256) | AB(128) | sq0(256), interleaved 2:3 ----
    {
        GemmDesc dAB = gd;
        dAB.A = P.A; dAB.Ars = 512; dAB.Amode = 0;
        dAB.B = P.Bm; dAB.Bks = 256; dAB.Bmode = 1;
        dAB.C = P.Bc + HB; dAB.Cis = 256; dAB.Cjs = 1;
        dAB.part = P.pC; dAB.slab = HB;
        dAB.M = 512; dAB.N = 256; dAB.K = 512; dAB.gx = 4; dAB.gy = 4; dAB.gz = 8;
        GemmDesc dS0 = sqDesc(0);
        for (int t = blockIdx.x; t < 640; t += NB) {
            int r5 = t % 5, q5 = t / 5;
            if (r5 < 2) ut_task(q5 * 2 + r5, P.Mm, P.Mbar, P.wv, P.out, As);
            else {
                int g = q5 * 3 + (r5 - 2);
                if (g < 128) gemm_block(dAB, g, As, Bs);
                else         gemm_block(dS0, g - 128, As, Bs);
            }
        }
    }
    gbar(bar++);

    // ---- St3: reduce AB + sq0 ----
    {
        RedDesc rAB = rd; rAB.dst = P.Bc + HB; rAB.part = P.pC;
        rAB.len = (int)HB; rAB.nz = 8; rAB.slab = HB;
        red_range(rAB, nullptr);
        red_range(sqRed(0), nullptr);
    }
    gbar(bar++);

    // ---- St4: A^2B(128) | A^3B(128) | sq1(256) ----
    {
        GemmDesc d2 = gd;
        d2.A = P.Ap; d2.Ars = 512; d2.Amode = 0;
        d2.B = P.Bm; d2.Bks = 256; d2.Bmode = 1;
        d2.C = P.Bc + 2 * HB; d2.Cis = 256; d2.Cjs = 1;
        d2.part = P.pC; d2.slab = HB;
        d2.M = 512; d2.N = 256; d2.K = 512; d2.gx = 4; d2.gy = 4; d2.gz = 8;
        GemmDesc d3 = d2;
        d3.B = P.Bc + HB;
        d3.C = P.Bc + 3 * HB;
        d3.part = P.pD;
        GemmDesc dS1 = sqDesc(1);
        for (int t = blockIdx.x; t < 512; t += NB) {
            if (t < 128)      gemm_block(d2, t, As, Bs);
            else if (t < 256) gemm_block(d3, t - 128, As, Bs);
            else              gemm_block(dS1, t - 256, As, Bs);
        }
    }
    gbar(bar++);

    // ---- St5: reduce A^2B, A^3B, sq1 ----
    {
        RedDesc r2 = rd; r2.dst = P.Bc + 2 * HB; r2.part = P.pC;
        r2.len = (int)HB; r2.nz = 8; r2.slab = HB;
        RedDesc r3 = r2; r3.dst = P.Bc + 3 * HB; r3.part = P.pD;
        red_range(r2, nullptr);
        red_range(r3, nullptr);
        red_range(sqRed(1), nullptr);
    }
    gbar(bar++);

    // ---- St6: W = Bcat x Ucat (256) | sq2(256) ----
    {
        GemmDesc dW = gd;
        dW.A = P.Bc; dW.Amode = 1;
        dW.B = P.uh; dW.Bmode = 2;
        dW.C = P.T0; dW.Cis = 1; dW.Cjs = 512;
        dW.part = P.pC; dW.slab = SQ;
        dW.M = 512; dW.N = 512; dW.K = 1024; dW.gx = 8; dW.gy = 4; dW.gz = 8;
        GemmDesc dS2 = sqDesc(2);
        for (int t = blockIdx.x; t < 512; t += NB) {
            if (t < 256) gemm_block(dW, t, As, Bs);
            else         gemm_block(dS2, t - 256, As, Bs);
        }
    }
    gbar(bar++);

    // ---- St7: reduce W + sq2 ----
    {
        RedDesc rW = rd; rW.dst = P.T0; rW.part = P.pC;
        rW.len = (int)SQ; rW.nz = 8; rW.slab = SQ;
        red_range(rW, nullptr);
        red_range(sqRed(2), nullptr);
    }
    gbar(bar++);

    // ---- tree levels k=0..8 ----
    float* bin = P.T0;
    float* bout = P.T1;
    for (int k = 0; k < 9; k++) {
        int Nk = 256 >> k;
        GemmDesc dL = gd;
        dL.A = P.Ap + (long long)(k + 1) * SQ; dL.Ars = 512; dL.Amode = 0;
        dL.B = bin + 512; dL.Bks = 1; dL.Bjs = 1024; dL.Bmode = 0;
        dL.C = bout; dL.Cis = 1; dL.Cjs = 512;
        dL.part = P.pC; dL.slab = (long long)512 * Nk;
        dL.M = 512; dL.N = Nk; dL.K = 512;
        dL.gx = (Nk + 63) / 64; dL.gy = 4; dL.gz = 8;
        int nL = dL.gx * 32;

        if (k <= 6) {
            GemmDesc dSq = sqDesc(k + 3);
            for (int t = blockIdx.x; t < nL + 256; t += NB) {
                if (t < nL) gemm_block(dL, t, As, Bs);
                else        gemm_block(dSq, t - nL, As, Bs);
            }
        } else {
            for (int t = blockIdx.x; t < nL; t += NB) gemm_block(dL, t, As, Bs);
        }
        gbar(bar++);

        RedDesc rL = rd;
        rL.dst = bout; rL.part = P.pC; rL.len = 512 * Nk; rL.nz = 8;
        rL.slab = (long long)512 * Nk;
        rL.Add = bin; rL.Adjs = 1024; rL.colMajor = 1;
        red_range(rL, (k == 1) ? P.Qb : nullptr);
        if (k <= 6) red_range(sqRed(k + 3), nullptr);
        gbar(bar++);

        float* tmp = bin; bin = bout; bout = tmp;
    }

    // ---- tail ----
    const float* sv = bin;
    for (int t = blockIdx.x; t < 512; t += NB)
        tail_task(t, P.Cm, P.yh + 2047 * 256, sv, P.Qb, P.out, As);
}

// =================================================================================
extern "C" void kernel_launch(void* const* d_in, const int* in_sizes, int n_in,
                              void* d_out, int out_size)
{
    Params P;
    P.A    = (const float*)d_in[0];
    P.Bm   = (const float*)d_in[1];
    P.Cm   = (const float*)d_in[2];
    P.Mm   = (const float*)d_in[3];
    P.Mbar = (const float*)d_in[4];
    P.sig  = (const float*)d_in[5];
    P.phi  = (const float*)d_in[6];
    P.lam  = (const float*)d_in[7];
    P.phit = (const float*)d_in[8];
    P.yh   = (const float*)d_in[9];
    P.uh   = (const float*)d_in[10];
    P.ynh  = (const float*)d_in[11];
    P.out  = (float*)d_out;

    cudaGetSymbolAddress((void**)&P.T0, g_T0);
    cudaGetSymbolAddress((void**)&P.T1, g_T1);
    cudaGetSymbolAddress((void**)&P.Ap, g_Apow);
    cudaGetSymbolAddress((void**)&P.Bc, g_Bcat);
    cudaGetSymbolAddress((void**)&P.Qb, g_Q);
    cudaGetSymbolAddress((void**)&P.S,  g_S);
    cudaGetSymbolAddress((void**)&P.wv, g_wv);
    cudaGetSymbolAddress((void**)&P.pS, g_pS);
    cudaGetSymbolAddress((void**)&P.pC, g_pC);
    cudaGetSymbolAddress((void**)&P.pD, g_pD);

    persist_kernel<<<NB, 256>>>(P);
}

// round 13
// speedup vs baseline: 1.0513x; 1.0513x over previous
#include <cuda_runtime.h>

#define NB 256

// ---------------- scratch (static device globals; no allocation) ----------------
__device__ float g_T0[512 * 512];
__device__ float g_T1[512 * 512];
__device__ float g_Apow[10 * 512 * 512];
__device__ float g_Bcat[4 * 512 * 256];
__device__ float g_Q[512];
__device__ float g_S[17 * 24 * 256];
__device__ float g_wv[306 * 256];
__device__ float g_pS[8 * 512 * 512];
__device__ float g_pC[8 * 512 * 512];
__device__ float g_pD[8 * 512 * 256];
__device__ unsigned g_hcnt[256];          // per-tile handoff counters (reset after use)

// ================= GEMM tile routine (128x64, 8x4 micro, double-buffered) ========
// Split-K=8 with deterministic in-kernel handoff: z=1..7 write partials + arrive;
// z=0 writes its partial, spins, then does a coalesced fixed-order 8-slab sum
// (+ optional Add), writes C (and optionally q = column 0).
struct GemmDesc {
    const float* A; long long Ars; int Amode;   // 0: A[m*Ars+k]; 1: cat4 [(k>>8)*131072 + m*256 + (k&255)]
    const float* B; long long Bks; long long Bjs;
    int Bmode;                                  // 0: B[k+n*Bjs]; 1: B[k*Bks+n]; 2: Ucat(u_history)
    float* C; long long Cis; long long Cjs;
    float* part; long long slab;                // if part: handoff split-K (gz slabs)
    const float* Add; long long Adjs;           // z0 adds Add[gm + gn*Adjs] (col-major C only)
    float* qdst;                                // if set (col-major): also write column 0
    int handBase;                               // counter base for this piece
    int M, N, K, gx, gy, gz;
};

__device__ void gemm_block(const GemmDesc& d, int r)
{
    __shared__ float As[2][16][132];
    __shared__ float Bs[2][16][72];

    const int tid = threadIdx.x;
    // z INNERMOST so the 8 partners of a tile are adjacent blockIdx (co-scheduled)
    const int z  = r % d.gz;
    const int bx = (r / d.gz) % d.gx;
    const int by = r / (d.gz * d.gx);
    const int bm = by * 128;
    const int bn = bx * 64;
    const int Kc = d.K / d.gz;
    const int kbeg = z * Kc;
    const int nt = Kc >> 4;

    const int arow = tid >> 1;
    const int akq  = (tid & 1) * 8;
    const int btn  = tid >> 2;
    const int btk  = (tid & 3) * 4;
    const int bkk  = tid >> 4;
    const int bn4  = (tid & 15) * 4;
    const int ty = tid >> 4, tx = tid & 15;

    float4 ax, ay, bv;

    auto loadA8 = [&](int kt) {
        int k = kbeg + kt + akq;
        const float* p = (d.Amode == 0)
            ? d.A + (long long)(bm + arow) * d.Ars + k
            : d.A + (long long)(k >> 8) * 131072 + (long long)(bm + arow) * 256 + (k & 255);
        ax = *(const float4*)p;
        ay = *(const float4*)(p + 4);
    };
    auto loadB4 = [&](int kt) {
        if (d.Bmode == 1) {
            bv = *(const float4*)(d.B + (long long)(kbeg + kt + bkk) * d.Bks + bn + bn4);
        } else if (d.Bmode == 0) {
            int n = bn + btn;
            bv = (n < d.N) ? *(const float4*)(d.B + (long long)(kbeg + kt + btk)
                                                + (long long)n * d.Bjs)
                           : make_float4(0.f, 0.f, 0.f, 0.f);
        } else {
            int n = bn + btn;
            int k = kbeg + kt + btk;
            if (n < d.N) {
                int tu = 2047 - 4 * n - (k >> 8);
                bv = *(const float4*)(d.B + (long long)tu * 256 + (k & 255));
            } else bv = make_float4(0.f, 0.f, 0.f, 0.f);
        }
    };
    auto stAB = [&](int buf) {
        float av[8] = {ax.x, ax.y, ax.z, ax.w, ay.x, ay.y, ay.z, ay.w};
        #pragma unroll
        for (int j = 0; j < 8; j++) As[buf][akq + j][arow] = av[j];
        if (d.Bmode == 1) {
            *(float4*)&Bs[buf][bkk][bn4] = bv;
        } else {
            float vv[4] = {bv.x, bv.y, bv.z, bv.w};
            #pragma unroll
            for (int j = 0; j < 4; j++) Bs[buf][btk + j][btn] = vv[j];
        }
    };

    loadA8(0); loadB4(0);
    stAB(0);
    __syncthreads();

    float acc[8][4] = {};

    for (int t = 0; t < nt; t++) {
        int cur = t & 1;
        if (t + 1 < nt) { loadA8((t + 1) * 16); loadB4((t + 1) * 16); }
        #pragma unroll
        for (int kk = 0; kk < 16; kk++) {
            float4 a4 = *(const float4*)&As[cur][kk][ty * 8];
            float4 a5 = *(const float4*)&As[cur][kk][ty * 8 + 4];
            float4 b4 = *(const float4*)&Bs[cur][kk][tx * 4];
            float av[8] = {a4.x, a4.y, a4.z, a4.w, a5.x, a5.y, a5.z, a5.w};
            float bw[4] = {b4.x, b4.y, b4.z, b4.w};
            #pragma unroll
            for (int i = 0; i < 8; i++)
                #pragma unroll
                for (int j = 0; j < 4; j++)
                    acc[i][j] = fmaf(av[i], bw[j], acc[i][j]);
        }
        if (t + 1 < nt) {
            __syncthreads();
            stAB(cur ^ 1);
            __syncthreads();
        }
    }

    if (!d.part) {
        // direct write (unused currently, kept for completeness)
        #pragma unroll
        for (int i = 0; i < 4; i++) {} // no-op
        if (d.Cjs == 1) {
            int gn = bn + tx * 4;
            if (gn < d.N)
                #pragma unroll
                for (int i = 0; i < 8; i++) {
                    int gm = bm + ty * 8 + i;
                    *(float4*)(d.C + (long long)gm * d.Cis + gn) =
                        make_float4(acc[i][0], acc[i][1], acc[i][2], acc[i][3]);
                }
        } else {
            #pragma unroll
            for (int j = 0; j < 4; j++) {
                int gn = bn + tx * 4 + j;
                if (gn < d.N) {
                    long long base = (long long)(bm + ty * 8) + (long long)gn * d.Cjs;
                    *(float4*)(d.C + base)     = make_float4(acc[0][j], acc[1][j], acc[2][j], acc[3][j]);
                    *(float4*)(d.C + base + 4) = make_float4(acc[4][j], acc[5][j], acc[6][j], acc[7][j]);
                }
            }
        }
        return;
    }

    // ---- write own partial to slab z ----
    float* outp = d.part + (long long)z * d.slab;
    if (d.Cjs == 1) {
        int gn = bn + tx * 4;
        if (gn < d.N)
            #pragma unroll
            for (int i = 0; i < 8; i++) {
                int gm = bm + ty * 8 + i;
                *(float4*)(outp + (long long)gm * d.Cis + gn) =
                    make_float4(acc[i][0], acc[i][1], acc[i][2], acc[i][3]);
            }
    } else {
        #pragma unroll
        for (int j = 0; j < 4; j++) {
            int gn = bn + tx * 4 + j;
            if (gn < d.N) {
                long long base = (long long)(bm + ty * 8) + (long long)gn * d.Cjs;
                *(float4*)(outp + base)     = make_float4(acc[0][j], acc[1][j], acc[2][j], acc[3][j]);
                *(float4*)(outp + base + 4) = make_float4(acc[4][j], acc[5][j], acc[6][j], acc[7][j]);
            }
        }
    }

    const int tileIdx = d.handBase + by * d.gx + bx;
    __threadfence();
    __syncthreads();

    if (z != 0) {
        if (tid == 0) atomicAdd(&g_hcnt[tileIdx], 1u);
        return;
    }

    // ---- z0: wait for partners, then fixed-order coalesced 8-slab sum ----
    if (tid == 0) {
        volatile unsigned* c = &g_hcnt[tileIdx];
        while (*c != (unsigned)(d.gz - 1)) __nanosleep(32);
    }
    __syncthreads();
    __threadfence();

    const int foot = 128 * 64;
    if (d.Cjs == 1) {                 // row-major: unit-n; N always fully covered here
        for (int lin = tid * 4; lin < foot; lin += 256 * 4) {
            int rr = lin >> 6, cc = lin & 63;
            long long addr = (long long)(bm + rr) * d.Cis + bn + cc;
            float4 a = *(const float4*)(d.part + addr);
            #pragma unroll
            for (int zz = 1; zz < 8; zz++) {
                float4 v = *(const float4*)(d.part + (long long)zz * d.slab + addr);
                a.x += v.x; a.y += v.y; a.z += v.z; a.w += v.w;
            }
            *(float4*)(d.C + addr) = a;
        }
    } else {                          // col-major: unit-m
        for (int lin = tid * 4; lin < foot; lin += 256 * 4) {
            int cc = lin >> 7, rr = lin & 127;
            int gn = bn + cc;
            if (gn >= d.N) continue;
            long long addr = (long long)(bm + rr) + (long long)gn * d.Cjs;
            float4 a = *(const float4*)(d.part + addr);
            #pragma unroll
            for (int zz = 1; zz < 8; zz++) {
                float4 v = *(const float4*)(d.part + (long long)zz * d.slab + addr);
                a.x += v.x; a.y += v.y; a.z += v.z; a.w += v.w;
            }
            if (d.Add) {
                const float* ap = d.Add + (bm + rr) + (long long)gn * d.Adjs;
                a.x += ap[0]; a.y += ap[1]; a.z += ap[2]; a.w += ap[3];
            }
            *(float4*)(d.C + addr) = a;
            if (d.qdst && gn == 0) *(float4*)(d.qdst + bm + rr) = a;
        }
    }
    __syncthreads();
    if (tid == 0) g_hcnt[tileIdx] = 0;   // replay-safe reset
}

// ---------------- ut block: 80 MB HBM-bound matvec -------------------------------
__device__ void ut_block(int n, const float* __restrict__ Mm, const float* __restrict__ Mbar,
                         const float* __restrict__ wv, float* __restrict__ out)
{
    __shared__ float sd[256];
    int p = threadIdx.x;
    float acc = 0.f;
    #pragma unroll 4
    for (int b = 0; b < 17; b++)
        acc += Mbar[((long long)b * 256 + n) * 256 + p] * wv[b * 256 + p];
    #pragma unroll 4
    for (int bb = 0; bb < 289; bb++)
        acc += Mm[((long long)bb * 256 + n) * 256 + p] * wv[(17 + bb) * 256 + p];
    sd[p] = acc;
    __syncthreads();
    for (int st = 128; st > 0; st >>= 1) {
        if (p < st) sd[p] += sd[p + st];
        __syncthreads();
    }
    if (p == 0) out[512 + n] = sd[0];
}

// -------- fused launch: ut chunk + up to 3 GEMM pieces (one task per block) ------
__global__ __launch_bounds__(256)
void mega_kernel(GemmDesc d0, GemmDesc d1, GemmDesc d2, int n0, int n1,
                 int nu, int nuOff,
                 const float* Mm, const float* Mbar, const float* wv, float* out)
{
    int b = blockIdx.x;
    if (b < nu) { ut_block(nuOff + b, Mm, Mbar, wv, out); return; }
    b -= nu;
    if (b < n0)            gemm_block(d0, b);
    else if (b < n0 + n1)  gemm_block(d1, b - n0);
    else                   gemm_block(d2, b - n0 - n1);
}

// ---------------- controller prep ------------------------------------------------
__global__ void s_kernel(const float* __restrict__ phi, const float* __restrict__ ynh,
                         float* __restrict__ S)
{
    int l = blockIdx.x / 24, j = blockIdx.x % 24, p = threadIdx.x;
    float acc = 0.f;
    #pragma unroll
    for (int k = 0; k < 25; k++)
        acc += phi[k * 17 + l] * ynh[(2047 - (2 + j + k)) * 256 + p];
    S[blockIdx.x * 256 + p] = acc;
}

__global__ void wv_kernel(const float* __restrict__ ynh, const float* __restrict__ S,
                          const float* __restrict__ phi, const float* __restrict__ phit,
                          const float* __restrict__ sig, const float* __restrict__ lam,
                          float* __restrict__ wv)
{
    int b = blockIdx.x, p = threadIdx.x;
    float v;
    if (b == 0) {
        v = ynh[2047 * 256 + p];
    } else if (b < 17) {
        int i = b - 1;
        float lam4 = sqrtf(sqrtf(lam[i]));
        float acc = 0.f;
        #pragma unroll
        for (int j = 0; j < 24; j++)
            acc += phit[j * 16 + i] * ynh[(2047 - 1 - j) * 256 + p];
        v = lam4 * acc;
    } else {
        int bb = b - 17, ip = bb / 17, l = bb % 17;
        float s4 = sqrtf(sqrtf(sig[l]));
        if (ip == 0) {
            float acc = 0.f;
            #pragma unroll
            for (int k = 0; k < 25; k++)
                acc += phi[k * 17 + l] * ynh[(2047 - k) * 256 + p];
            v = s4 * acc;
        } else {
            int i = ip - 1;
            float lam4 = sqrtf(sqrtf(lam[i]));
            float acc = 0.f;
            #pragma unroll
            for (int j = 0; j < 24; j++)
                acc += phit[j * 16 + i] * S[(l * 24 + j) * 256 + p];
            v = lam4 * s4 * acc;
        }
    }
    wv[b * 256 + p] = v;
}

// ---------------- y_nat / pred ---------------------------------------------------
__global__ void ynat_pred_kernel(const float* __restrict__ Cm, const float* __restrict__ ylast,
                                 const float* __restrict__ s, const float* __restrict__ q,
                                 float* __restrict__ out)
{
    int row = blockIdx.x;
    int p = row & 255;
    bool isPred = row >= 256;
    const float* cr = Cm + p * 512;
    float acc = 0.f;
    for (int d = threadIdx.x; d < 512; d += 128) {
        float x = isPred ? (q[d] - s[d]) : (-s[d]);
        acc += cr[d] * x;
    }
    __shared__ float sd[128];
    sd[threadIdx.x] = acc;
    __syncthreads();
    for (int st = 64; st > 0; st >>= 1) {
        if (threadIdx.x < st) sd[threadIdx.x] += sd[threadIdx.x + st];
        __syncthreads();
    }
    if (threadIdx.x == 0) out[row] = ylast[p] + sd[0];
}

// =================================================================================
extern "C" void kernel_launch(void* const* d_in, const int* in_sizes, int n_in,
                              void* d_out, int out_size)
{
    const float* A    = (const float*)d_in[0];
    const float* Bm   = (const float*)d_in[1];
    const float* Cm   = (const float*)d_in[2];
    const float* Mm   = (const float*)d_in[3];
    const float* Mbar = (const float*)d_in[4];
    const float* sig  = (const float*)d_in[5];
    const float* phi  = (const float*)d_in[6];
    const float* lam  = (const float*)d_in[7];
    const float* phit = (const float*)d_in[8];
    const float* yh   = (const float*)d_in[9];
    const float* uh   = (const float*)d_in[10];
    const float* ynh  = (const float*)d_in[11];
    float* out = (float*)d_out;

    float *T0, *T1, *Ap, *Bc, *Qb, *S, *wv, *pS, *pC, *pD;
    cudaGetSymbolAddress((void**)&T0, g_T0);
    cudaGetSymbolAddress((void**)&T1, g_T1);
    cudaGetSymbolAddress((void**)&Ap, g_Apow);
    cudaGetSymbolAddress((void**)&Bc, g_Bcat);
    cudaGetSymbolAddress((void**)&Qb, g_Q);
    cudaGetSymbolAddress((void**)&S,  g_S);
    cudaGetSymbolAddress((void**)&wv, g_wv);
    cudaGetSymbolAddress((void**)&pS, g_pS);
    cudaGetSymbolAddress((void**)&pC, g_pC);
    cudaGetSymbolAddress((void**)&pD, g_pD);

    const long long SQ = 512 * 512;
    const long long HB = 512 * 256;

    GemmDesc gd = {}; gd.gx = gd.gy = gd.gz = 1;

    auto sqDesc = [&](int k, int hbase) {    // Ap[k] = Ak^2
        GemmDesc d = gd;
        const float* src = (k == 0) ? A : Ap + (long long)(k - 1) * SQ;
        d.A = src; d.Ars = 512; d.Amode = 0;
        d.B = src; d.Bks = 512; d.Bmode = 1;
        d.C = Ap + (long long)k * SQ; d.Cis = 512; d.Cjs = 1;
        d.part = pS; d.slab = SQ; d.handBase = hbase;
        d.M = 512; d.N = 512; d.K = 512; d.gx = 8; d.gy = 4; d.gz = 8;
        return d;
    };

    // ---- prep ----
    s_kernel<<<17 * 24, 256>>>(phi, ynh, S);
    cudaMemcpyAsync(Bc, Bm, HB * sizeof(float), cudaMemcpyDeviceToDevice);
    wv_kernel<<<306, 256>>>(ynh, S, phi, phit, sig, lam, wv);

    // ---- F1: ut[0,86) | AB (16 tiles x8) | sq0 (32 tiles x8) ----
    {
        GemmDesc dAB = gd;
        dAB.A = A; dAB.Ars = 512; dAB.Amode = 0;
        dAB.B = Bm; dAB.Bks = 256; dAB.Bmode = 1;
        dAB.C = Bc + HB; dAB.Cis = 256; dAB.Cjs = 1;
        dAB.part = pC; dAB.slab = HB; dAB.handBase = 0;
        dAB.M = 512; dAB.N = 256; dAB.K = 512; dAB.gx = 4; dAB.gy = 4; dAB.gz = 8;
        GemmDesc dS0 = sqDesc(0, 16);
        mega_kernel<<<86 + 128 + 256, 256>>>(dAB, dS0, gd, 128, 256, 86, 0,
                                             Mm, Mbar, wv, out);
    }

    // ---- F2: ut[86,171) | A^2B | A^3B | sq1 ----
    {
        GemmDesc d2 = gd;
        d2.A = Ap; d2.Ars = 512; d2.Amode = 0;
        d2.B = Bm; d2.Bks = 256; d2.Bmode = 1;
        d2.C = Bc + 2 * HB; d2.Cis = 256; d2.Cjs = 1;
        d2.part = pC; d2.slab = HB; d2.handBase = 0;
        d2.M = 512; d2.N = 256; d2.K = 512; d2.gx = 4; d2.gy = 4; d2.gz = 8;
        GemmDesc d3 = d2;
        d3.B = Bc + HB;
        d3.C = Bc + 3 * HB;
        d3.part = pD; d3.handBase = 16;
        GemmDesc dS1 = sqDesc(1, 32);
        mega_kernel<<<85 + 128 + 128 + 256, 256>>>(d2, d3, dS1, 128, 128, 85, 86,
                                                   Mm, Mbar, wv, out);
    }

    // ---- F3: ut[171,256) | W = Bcat x Ucat (32 tiles) | sq2 ----
    {
        GemmDesc dW = gd;
        dW.A = Bc; dW.Amode = 1;
        dW.B = uh; dW.Bmode = 2;
        dW.C = T0; dW.Cis = 1; dW.Cjs = 512;
        dW.part = pC; dW.slab = SQ; dW.handBase = 0;
        dW.M = 512; dW.N = 512; dW.K = 1024; dW.gx = 8; dW.gy = 4; dW.gz = 8;
        GemmDesc dS2 = sqDesc(2, 32);
        mega_kernel<<<85 + 256 + 256, 256>>>(dW, dS2, gd, 256, 256, 85, 171,
                                             Mm, Mbar, wv, out);
    }

    // ---- tree levels k=0..8: X_m <- X_{2m} + A^(2^(k+2)) X_{2m+1} ----
    float* bin = T0;
    float* bout = T1;
    for (int k = 0; k < 9; k++) {
        int Nk = 256 >> k;
        GemmDesc dL = gd;
        dL.A = Ap + (long long)(k + 1) * SQ; dL.Ars = 512; dL.Amode = 0;
        dL.B = bin + 512; dL.Bks = 1; dL.Bjs = 1024; dL.Bmode = 0;
        dL.C = bout; dL.Cis = 1; dL.Cjs = 512;
        dL.part = pC; dL.slab = (long long)512 * Nk; dL.handBase = 0;
        dL.Add = bin; dL.Adjs = 1024;
        dL.qdst = (k == 1) ? Qb : nullptr;
        dL.M = 512; dL.N = Nk; dL.K = 512;
        dL.gx = (Nk + 63) / 64; dL.gy = 4; dL.gz = 8;
        int nL = dL.gx * 4 * 8;

        if (k <= 6) {
            GemmDesc dSq = sqDesc(k + 3, 16);
            mega_kernel<<<nL + 256, 256>>>(dL, dSq, gd, nL, 256, 0, 0,
                                           Mm, Mbar, wv, out);
        } else {
            mega_kernel<<<nL, 256>>>(dL, gd, gd, nL, 0, 0, 0,
                                     Mm, Mbar, wv, out);
        }
        float* tmp = bin; bin = bout; bout = tmp;
    }
    const float* sv = bin;   // s = column 0 of final level

    // ---- tail: y_nat = y_last - C s ; pred = y_last + C (q - s) ----
    ynat_pred_kernel<<<512, 128>>>(Cm, yh + 2047 * 256, sv, Qb, out);
}

// round 14
// speedup vs baseline: 1.3843x; 1.3167x over previous
#include <cuda_runtime.h>

// ---------------- scratch (static device globals; no allocation) ----------------
__device__ float g_T0[512 * 512];
__device__ float g_T1[512 * 512];
__device__ float g_Apow[10 * 512 * 512];
__device__ float g_Bcat[4 * 512 * 256];
__device__ float g_Q[512];
__device__ float g_S[17 * 24 * 256];
__device__ float g_wv[306 * 256];
__device__ float g_utp[256 * 18];        // ut partial sums
__device__ float g_pS[8 * 512 * 512];
__device__ float g_pC[8 * 512 * 512];
__device__ float g_pD[8 * 512 * 256];

// ================= GEMM descriptor + tile routine (128x64, 8x4, dbuf) ===========
struct GemmDesc {
    const float* A; long long Ars; int Amode;   // 0: A[m*Ars+k]; 1: cat4 [(k>>8)*131072 + m*256 + (k&255)]
    const float* B; long long Bks; long long Bjs;
    int Bmode;                                  // 0: B[k+n*Bjs]; 1: B[k*Bks+n]; 2: Ucat(u_history)
    float* C; long long Cis; long long Cjs;
    float* part; long long slab;
    int M, N, K, gx, gy, gz;
};

__device__ void gemm_block(const GemmDesc& d, int r)
{
    __shared__ float As[2][16][132];
    __shared__ float Bs[2][16][72];

    const int tid = threadIdx.x;
    const int bx = r % d.gx;
    const int by = (r / d.gx) % d.gy;
    const int z  = r / (d.gx * d.gy);
    const int bm = by * 128;
    const int bn = bx * 64;
    const int Kc = d.K / d.gz;
    const int kbeg = z * Kc;
    const int nt = Kc >> 4;

    const int arow = tid >> 1;
    const int akq  = (tid & 1) * 8;
    const int btn  = tid >> 2;
    const int btk  = (tid & 3) * 4;
    const int bkk  = tid >> 4;
    const int bn4  = (tid & 15) * 4;
    const int ty = tid >> 4, tx = tid & 15;

    float4 ax, ay, bv;

    auto loadA8 = [&](int kt) {
        int k = kbeg + kt + akq;
        const float* p = (d.Amode == 0)
            ? d.A + (long long)(bm + arow) * d.Ars + k
            : d.A + (long long)(k >> 8) * 131072 + (long long)(bm + arow) * 256 + (k & 255);
        ax = *(const float4*)p;
        ay = *(const float4*)(p + 4);
    };
    auto loadB4 = [&](int kt) {
        if (d.Bmode == 1) {
            bv = *(const float4*)(d.B + (long long)(kbeg + kt + bkk) * d.Bks + bn + bn4);
        } else if (d.Bmode == 0) {
            int n = bn + btn;
            bv = (n < d.N) ? *(const float4*)(d.B + (long long)(kbeg + kt + btk)
                                                + (long long)n * d.Bjs)
                           : make_float4(0.f, 0.f, 0.f, 0.f);
        } else {
            int n = bn + btn;
            int k = kbeg + kt + btk;
            if (n < d.N) {
                int tu = 2047 - 4 * n - (k >> 8);
                bv = *(const float4*)(d.B + (long long)tu * 256 + (k & 255));
            } else bv = make_float4(0.f, 0.f, 0.f, 0.f);
        }
    };
    auto stAB = [&](int buf) {
        float av[8] = {ax.x, ax.y, ax.z, ax.w, ay.x, ay.y, ay.z, ay.w};
        #pragma unroll
        for (int j = 0; j < 8; j++) As[buf][akq + j][arow] = av[j];
        if (d.Bmode == 1) {
            *(float4*)&Bs[buf][bkk][bn4] = bv;
        } else {
            float vv[4] = {bv.x, bv.y, bv.z, bv.w};
            #pragma unroll
            for (int j = 0; j < 4; j++) Bs[buf][btk + j][btn] = vv[j];
        }
    };

    loadA8(0); loadB4(0);
    stAB(0);
    __syncthreads();

    float acc[8][4] = {};

    for (int t = 0; t < nt; t++) {
        int cur = t & 1;
        if (t + 1 < nt) { loadA8((t + 1) * 16); loadB4((t + 1) * 16); }
        #pragma unroll
        for (int kk = 0; kk < 16; kk++) {
            float4 a4 = *(const float4*)&As[cur][kk][ty * 8];
            float4 a5 = *(const float4*)&As[cur][kk][ty * 8 + 4];
            float4 b4 = *(const float4*)&Bs[cur][kk][tx * 4];
            float av[8] = {a4.x, a4.y, a4.z, a4.w, a5.x, a5.y, a5.z, a5.w};
            float bw[4] = {b4.x, b4.y, b4.z, b4.w};
            #pragma unroll
            for (int i = 0; i < 8; i++)
                #pragma unroll
                for (int j = 0; j < 4; j++)
                    acc[i][j] = fmaf(av[i], bw[j], acc[i][j]);
        }
        if (t + 1 < nt) {
            __syncthreads();
            stAB(cur ^ 1);
            __syncthreads();
        }
    }

    float* outp = d.part ? d.part + (long long)z * d.slab : d.C;
    if (d.Cjs == 1) {
        int gn = bn + tx * 4;
        if (gn < d.N) {
            #pragma unroll
            for (int i = 0; i < 8; i++) {
                int gm = bm + ty * 8 + i;
                *(float4*)(outp + (long long)gm * d.Cis + gn) =
                    make_float4(acc[i][0], acc[i][1], acc[i][2], acc[i][3]);
            }
        }
    } else {
        #pragma unroll
        for (int j = 0; j < 4; j++) {
            int gn = bn + tx * 4 + j;
            if (gn < d.N) {
                long long base = (long long)(bm + ty * 8) + (long long)gn * d.Cjs;
                *(float4*)(outp + base)     = make_float4(acc[0][j], acc[1][j], acc[2][j], acc[3][j]);
                *(float4*)(outp + base + 4) = make_float4(acc[4][j], acc[5][j], acc[6][j], acc[7][j]);
            }
        }
    }
}

// ---------------- ut partial: 4608 CTAs, MLP-17 streaming ------------------------
__device__ void utp_task(int t, const float* __restrict__ Mm, const float* __restrict__ Mbar,
                         const float* __restrict__ wv, float* __restrict__ utp)
{
    __shared__ float sd[256];
    int n = t / 18, c = t % 18;
    int p = threadIdx.x;
    float acc = 0.f;
    #pragma unroll
    for (int j = 0; j < 17; j++) {
        int bb = c * 17 + j;
        const float* Mat = (bb < 17)
            ? (Mbar + ((long long)bb * 256 + n) * 256)
            : (Mm + ((long long)(bb - 17) * 256 + n) * 256);
        acc += Mat[p] * wv[bb * 256 + p];
    }
    sd[p] = acc;
    __syncthreads();
    for (int st = 128; st > 0; st >>= 1) {
        if (p < st) sd[p] += sd[p + st];
        __syncthreads();
    }
    if (p == 0) utp[n * 18 + c] = sd[0];
}

// ---------------- ut final: one block sums 18 partials per n ---------------------
__device__ void utfin_task(const float* __restrict__ utp, float* __restrict__ out)
{
    int t = threadIdx.x;   // 0..255 = n
    float a = 0.f;
    #pragma unroll
    for (int c = 0; c < 18; c++) a += utp[t * 18 + c];
    out[512 + t] = a;
}

// -------- fused launch: up to 3 GEMM pieces + ut partials + optional ut final ----
__global__ __launch_bounds__(256)
void mega_kernel(GemmDesc d0, GemmDesc d1, GemmDesc d2, int n0, int n1, int n2,
                 int nutp, int utpOff, int dofin,
                 const float* Mm, const float* Mbar, const float* wv,
                 float* utp, float* out)
{
    int b = blockIdx.x;
    int ng = n0 + n1 + n2;
    if (b < n0)            { gemm_block(d0, b); return; }
    if (b < n0 + n1)       { gemm_block(d1, b - n0); return; }
    if (b < ng)            { gemm_block(d2, b - n0 - n1); return; }
    b -= ng;
    if (b < nutp)          { utp_task(utpOff + b, Mm, Mbar, wv, utp); return; }
    if (dofin && b == nutp) utfin_task(utp, out);
}

// ================= fused split-K reduce ==========================================
struct RedDesc {
    float* dst; const float* part;
    int len; int nz; long long slab;
    const float* Add; long long Adjs; int colMajor;
};

__device__ __forceinline__ void red_elem(const RedDesc& r, int g)
{
    int i = g * 4;
    float4 acc;
    if (r.nz == 8) {
        float4 v[8];
        #pragma unroll
        for (int zz = 0; zz < 8; zz++)
            v[zz] = *(const float4*)(r.part + (long long)zz * r.slab + i);
        acc = v[0];
        #pragma unroll
        for (int zz = 1; zz < 8; zz++) {
            acc.x += v[zz].x; acc.y += v[zz].y; acc.z += v[zz].z; acc.w += v[zz].w;
        }
    } else {
        acc = *(const float4*)(r.part + i);
        for (int zz = 1; zz < r.nz; zz++) {
            float4 v = *(const float4*)(r.part + (long long)zz * r.slab + i);
            acc.x += v.x; acc.y += v.y; acc.z += v.z; acc.w += v.w;
        }
    }
    if (r.Add && r.colMajor) {
        int gm = i & 511, gn = i >> 9;
        const float* ap = r.Add + gm + (long long)gn * r.Adjs;
        acc.x += ap[0]; acc.y += ap[1]; acc.z += ap[2]; acc.w += ap[3];
    }
    *(float4*)(r.dst + i) = acc;
}

__global__ __launch_bounds__(256)
void fusedred_kernel(RedDesc r0, RedDesc r1, RedDesc r2, int c0, int c1, int c2)
{
    int g = blockIdx.x * 256 + threadIdx.x;
    if (g < c0)                 red_elem(r0, g);
    else if (g < c0 + c1)       red_elem(r1, g - c0);
    else if (g < c0 + c1 + c2)  red_elem(r2, g - c0 - c1);
}

// ---------------- controller prep ------------------------------------------------
__global__ void s_kernel(const float* __restrict__ phi, const float* __restrict__ ynh,
                         float* __restrict__ S)
{
    int l = blockIdx.x / 24, j = blockIdx.x % 24, p = threadIdx.x;
    float acc = 0.f;
    #pragma unroll
    for (int k = 0; k < 25; k++)
        acc += phi[k * 17 + l] * ynh[(2047 - (2 + j + k)) * 256 + p];
    S[blockIdx.x * 256 + p] = acc;
}

__global__ void wv_kernel(const float* __restrict__ ynh, const float* __restrict__ S,
                          const float* __restrict__ phi, const float* __restrict__ phit,
                          const float* __restrict__ sig, const float* __restrict__ lam,
                          float* __restrict__ wv)
{
    int b = blockIdx.x, p = threadIdx.x;
    float v;
    if (b == 0) {
        v = ynh[2047 * 256 + p];
    } else if (b < 17) {
        int i = b - 1;
        float lam4 = sqrtf(sqrtf(lam[i]));
        float acc = 0.f;
        #pragma unroll
        for (int j = 0; j < 24; j++)
            acc += phit[j * 16 + i] * ynh[(2047 - 1 - j) * 256 + p];
        v = lam4 * acc;
    } else {
        int bb = b - 17, ip = bb / 17, l = bb % 17;
        float s4 = sqrtf(sqrtf(sig[l]));
        if (ip == 0) {
            float acc = 0.f;
            #pragma unroll
            for (int k = 0; k < 25; k++)
                acc += phi[k * 17 + l] * ynh[(2047 - k) * 256 + p];
            v = s4 * acc;
        } else {
            int i = ip - 1;
            float lam4 = sqrtf(sqrtf(lam[i]));
            float acc = 0.f;
            #pragma unroll
            for (int j = 0; j < 24; j++)
                acc += phit[j * 16 + i] * S[(l * 24 + j) * 256 + p];
            v = lam4 * s4 * acc;
        }
    }
    wv[b * 256 + p] = v;
}

// ---------------- y_nat / pred ---------------------------------------------------
__global__ void ynat_pred_kernel(const float* __restrict__ Cm, const float* __restrict__ ylast,
                                 const float* __restrict__ s, const float* __restrict__ q,
                                 float* __restrict__ out)
{
    int row = blockIdx.x;
    int p = row & 255;
    bool isPred = row >= 256;
    const float* cr = Cm + p * 512;
    float acc = 0.f;
    for (int d = threadIdx.x; d < 512; d += 128) {
        float x = isPred ? (q[d] - s[d]) : (-s[d]);
        acc += cr[d] * x;
    }
    __shared__ float sd[128];
    sd[threadIdx.x] = acc;
    __syncthreads();
    for (int st = 64; st > 0; st >>= 1) {
        if (threadIdx.x < st) sd[threadIdx.x] += sd[threadIdx.x + st];
        __syncthreads();
    }
    if (threadIdx.x == 0) out[row] = ylast[p] + sd[0];
}

// =================================================================================
extern "C" void kernel_launch(void* const* d_in, const int* in_sizes, int n_in,
                              void* d_out, int out_size)
{
    const float* A    = (const float*)d_in[0];
    const float* Bm   = (const float*)d_in[1];
    const float* Cm   = (const float*)d_in[2];
    const float* Mm   = (const float*)d_in[3];
    const float* Mbar = (const float*)d_in[4];
    const float* sig  = (const float*)d_in[5];
    const float* phi  = (const float*)d_in[6];
    const float* lam  = (const float*)d_in[7];
    const float* phit = (const float*)d_in[8];
    const float* yh   = (const float*)d_in[9];
    const float* uh   = (const float*)d_in[10];
    const float* ynh  = (const float*)d_in[11];
    float* out = (float*)d_out;

    float *T0, *T1, *Ap, *Bc, *Qb, *S, *wv, *utp, *pS, *pC, *pD;
    cudaGetSymbolAddress((void**)&T0, g_T0);
    cudaGetSymbolAddress((void**)&T1, g_T1);
    cudaGetSymbolAddress((void**)&Ap, g_Apow);
    cudaGetSymbolAddress((void**)&Bc, g_Bcat);
    cudaGetSymbolAddress((void**)&Qb, g_Q);
    cudaGetSymbolAddress((void**)&S,  g_S);
    cudaGetSymbolAddress((void**)&wv, g_wv);
    cudaGetSymbolAddress((void**)&utp, g_utp);
    cudaGetSymbolAddress((void**)&pS, g_pS);
    cudaGetSymbolAddress((void**)&pC, g_pC);
    cudaGetSymbolAddress((void**)&pD, g_pD);

    const long long SQ = 512 * 512;
    const long long HB = 512 * 256;

    GemmDesc gd = {}; gd.gx = gd.gy = gd.gz = 1;
    RedDesc  rd = {};

    auto sqDesc = [&](int k) {
        GemmDesc d = gd;
        const float* src = (k == 0) ? A : Ap + (long long)(k - 1) * SQ;
        d.A = src; d.Ars = 512; d.Amode = 0;
        d.B = src; d.Bks = 512; d.Bmode = 1;
        d.C = Ap + (long long)k * SQ; d.Cis = 512; d.Cjs = 1;
        d.part = pS; d.slab = SQ;
        d.M = 512; d.N = 512; d.K = 512; d.gx = 8; d.gy = 4; d.gz = 8;
        return d;
    };
    auto sqRed = [&](int k) {
        RedDesc r = rd;
        r.dst = Ap + (long long)k * SQ; r.part = pS;
        r.len = (int)SQ; r.nz = 8; r.slab = SQ;
        return r;
    };

    // ---- prep ----
    s_kernel<<<17 * 24, 256>>>(phi, ynh, S);
    cudaMemcpyAsync(Bc, Bm, HB * sizeof(float), cudaMemcpyDeviceToDevice);
    wv_kernel<<<306, 256>>>(ynh, S, phi, phit, sig, lam, wv);

    // ---- F1: AB(128) | sq0(256) | ut partials (4608) ----
    {
        GemmDesc dAB = gd;
        dAB.A = A; dAB.Ars = 512; dAB.Amode = 0;
        dAB.B = Bm; dAB.Bks = 256; dAB.Bmode = 1;
        dAB.C = Bc + HB; dAB.Cis = 256; dAB.Cjs = 1;
        dAB.part = pC; dAB.slab = HB;
        dAB.M = 512; dAB.N = 256; dAB.K = 512; dAB.gx = 4; dAB.gy = 4; dAB.gz = 8;
        GemmDesc dS0 = sqDesc(0);
        mega_kernel<<<128 + 256 + 4608, 256>>>(dAB, dS0, gd, 128, 256, 0,
                                               4608, 0, 0, Mm, Mbar, wv, utp, out);

        RedDesc rAB = rd; rAB.dst = Bc + HB; rAB.part = pC;
        rAB.len = (int)HB; rAB.nz = 8; rAB.slab = HB;
        RedDesc rS0 = sqRed(0);
        int c0 = (int)HB / 4, c1 = (int)SQ / 4;
        fusedred_kernel<<<(c0 + c1 + 255) / 256, 256>>>(rAB, rS0, rd, c0, c1, 0);
    }

    // ---- F2: A^2B(128) | A^3B(128) | sq1(256) | ut final (1) ----
    {
        GemmDesc d2 = gd;
        d2.A = Ap; d2.Ars = 512; d2.Amode = 0;
        d2.B = Bm; d2.Bks = 256; d2.Bmode = 1;
        d2.C = Bc + 2 * HB; d2.Cis = 256; d2.Cjs = 1;
        d2.part = pC; d2.slab = HB;
        d2.M = 512; d2.N = 256; d2.K = 512; d2.gx = 4; d2.gy = 4; d2.gz = 8;
        GemmDesc d3 = d2;
        d3.B = Bc + HB;
        d3.C = Bc + 3 * HB;
        d3.part = pD;
        GemmDesc dS1 = sqDesc(1);
        mega_kernel<<<128 + 128 + 256 + 1, 256>>>(d2, d3, dS1, 128, 128, 256,
                                                  0, 0, 1, Mm, Mbar, wv, utp, out);

        RedDesc r2 = rd; r2.dst = Bc + 2 * HB; r2.part = pC;
        r2.len = (int)HB; r2.nz = 8; r2.slab = HB;
        RedDesc r3 = r2; r3.dst = Bc + 3 * HB; r3.part = pD;
        RedDesc rS1 = sqRed(1);
        int c0 = (int)HB / 4, c2 = (int)SQ / 4;
        fusedred_kernel<<<(c0 + c0 + c2 + 255) / 256, 256>>>(r2, r3, rS1, c0, c0, c2);
    }

    // ---- F3: W = Bcat x Ucat (256) | sq2(256) ----
    {
        GemmDesc dW = gd;
        dW.A = Bc; dW.Amode = 1;
        dW.B = uh; dW.Bmode = 2;
        dW.C = T0; dW.Cis = 1; dW.Cjs = 512;
        dW.part = pC; dW.slab = SQ;
        dW.M = 512; dW.N = 512; dW.K = 1024; dW.gx = 8; dW.gy = 4; dW.gz = 8;
        GemmDesc dS2 = sqDesc(2);
        mega_kernel<<<256 + 256, 256>>>(dW, dS2, gd, 256, 256, 0,
                                        0, 0, 0, Mm, Mbar, wv, utp, out);

        RedDesc rW = rd; rW.dst = T0; rW.part = pC;
        rW.len = (int)SQ; rW.nz = 8; rW.slab = SQ;
        RedDesc rS2 = sqRed(2);
        int c = (int)SQ / 4;
        fusedred_kernel<<<(2 * c + 255) / 256, 256>>>(rW, rS2, rd, c, c, 0);
    }

    // ---- tree levels k=0..8: X_m <- X_{2m} + A^(2^(k+2)) X_{2m+1} ----
    float* bin = T0;
    float* bout = T1;
    for (int k = 0; k < 9; k++) {
        int Nk = 256 >> k;
        GemmDesc dL = gd;
        dL.A = Ap + (long long)(k + 1) * SQ; dL.Ars = 512; dL.Amode = 0;
        dL.B = bin + 512; dL.Bks = 1; dL.Bjs = 1024; dL.Bmode = 0;
        dL.C = bout; dL.Cis = 1; dL.Cjs = 512;
        dL.part = pC; dL.slab = (long long)512 * Nk;
        dL.M = 512; dL.N = Nk; dL.K = 512;
        dL.gx = (Nk + 63) / 64; dL.gy = 4; dL.gz = 8;
        int nL = dL.gx * 4 * 8;

        RedDesc rL = rd;
        rL.dst = bout; rL.part = pC; rL.len = 512 * Nk; rL.nz = 8;
        rL.slab = (long long)512 * Nk;
        rL.Add = bin; rL.Adjs = 1024; rL.colMajor = 1;
        int cL = rL.len / 4;

        if (k <= 6) {
            GemmDesc dSq = sqDesc(k + 3);
            mega_kernel<<<nL + 256, 256>>>(dL, dSq, gd, nL, 256, 0,
                                           0, 0, 0, Mm, Mbar, wv, utp, out);
            RedDesc rSq = sqRed(k + 3);
            int cS = (int)SQ / 4;
            fusedred_kernel<<<(cL + cS + 255) / 256, 256>>>(rL, rSq, rd, cL, cS, 0);
        } else {
            mega_kernel<<<nL, 256>>>(dL, gd, gd, nL, 0, 0,
                                     0, 0, 0, Mm, Mbar, wv, utp, out);
            fusedred_kernel<<<(cL + 255) / 256, 256>>>(rL, rd, rd, cL, 0, 0);
        }

        if (k == 1)   // q = X^2 column 0
            cudaMemcpyAsync(Qb, bout, 512 * sizeof(float), cudaMemcpyDeviceToDevice);

        float* tmp = bin; bin = bout; bout = tmp;
    }
    const float* sv = bin;   // s = column 0 of final level

    // ---- tail: y_nat = y_last - C s ; pred = y_last + C (q - s) ----
    ynat_pred_kernel<<<512, 128>>>(Cm, yh + 2047 * 256, sv, Qb, out);
}